// round 1
// baseline (speedup 1.0000x reference)
#include <cuda_runtime.h>
#include <math.h>

#define NS 2048      // speakers
#define NG 8         // utts per speaker
#define ND 128       // embed dim
#define NR (NS*NG)   // 16384 rows
#define BM 64
#define BN 64

// Scratch (device globals; no allocation allowed)
__device__ float g_xnT[ND * NR];    // [k][r]  normalized x, k-major
__device__ float g_centT[ND * NS];  // [k][t]  normalized centroids * 30, k-major
__device__ float g_lbl[NR];         // label logit per row = max(30*cos_exc, 1e-6)

// ---------------------------------------------------------------------------
// f32x2 helpers
// ---------------------------------------------------------------------------
typedef unsigned long long ull;

__device__ __forceinline__ ull pack_dup(float v) {
    ull r; asm("mov.b64 %0, {%1, %1};" : "=l"(r) : "f"(v)); return r;
}
__device__ __forceinline__ ull fma2(ull a, ull b, ull c) {
    ull d; asm("fma.rn.f32x2 %0, %1, %2, %3;" : "=l"(d) : "l"(a), "l"(b), "l"(c)); return d;
}
__device__ __forceinline__ float2 unpack2(ull v) {
    float2 f; asm("mov.b64 {%0, %1}, %2;" : "=f"(f.x), "=f"(f.y) : "l"(v)); return f;
}

// ---------------------------------------------------------------------------
// Kernel 1: per-speaker prep. One block (128 threads) per speaker.
// Thread j owns dimension j for all 8 utterances.
// ---------------------------------------------------------------------------
__device__ __forceinline__ void reduce8(const float v[NG], float (*scr)[4],
                                        float* out8, int lane, int warp, int tid) {
    #pragma unroll
    for (int g = 0; g < NG; g++) {
        float r = v[g];
        #pragma unroll
        for (int off = 16; off > 0; off >>= 1)
            r += __shfl_xor_sync(0xffffffffu, r, off);
        if (lane == 0) scr[g][warp] = r;
    }
    __syncthreads();
    if (tid < NG) out8[tid] = scr[tid][0] + scr[tid][1] + scr[tid][2] + scr[tid][3];
    __syncthreads();
}

__global__ void prep_kernel(const float* __restrict__ x, float* __restrict__ out) {
    __shared__ float scr[NG][4];
    __shared__ float out8[NG];
    __shared__ float cnorm2;

    const int s    = blockIdx.x;
    const int j    = threadIdx.x;       // 0..127
    const int lane = j & 31;
    const int warp = j >> 5;

    float xg[NG];
    #pragma unroll
    for (int g = 0; g < NG; g++) xg[g] = x[(s * NG + g) * ND + j];

    // row norms
    float v[NG];
    #pragma unroll
    for (int g = 0; g < NG; g++) v[g] = xg[g] * xg[g];
    reduce8(v, scr, out8, lane, warp, j);
    float xn[NG];
    float sum = 0.f;
    #pragma unroll
    for (int g = 0; g < NG; g++) {
        float nrm = fmaxf(sqrtf(out8[g]), 1e-12f);
        xn[g] = xg[g] / nrm;
        sum += xn[g];
    }

    // centroid (mean of normalized rows), then normalize + pre-scale by 30
    float cent = sum * 0.125f;
    {
        float c2 = cent * cent;
        #pragma unroll
        for (int off = 16; off > 0; off >>= 1)
            c2 += __shfl_xor_sync(0xffffffffu, c2, off);
        if (lane == 0) scr[0][warp] = c2;
        __syncthreads();
        if (j == 0) cnorm2 = scr[0][0] + scr[0][1] + scr[0][2] + scr[0][3];
        __syncthreads();
    }
    g_centT[j * NS + s] = 30.f * cent / fmaxf(sqrtf(cnorm2), 1e-8f);

    // exclusive centroids
    float exc[NG];
    #pragma unroll
    for (int g = 0; g < NG; g++) {
        exc[g] = (sum - xn[g]) * (1.0f / 7.0f);
        v[g] = exc[g] * exc[g];
    }
    reduce8(v, scr, out8, lane, warp, j);
    float e2[NG];
    #pragma unroll
    for (int g = 0; g < NG; g++) e2[g] = out8[g];

    // cosine vs exclusive centroid
    #pragma unroll
    for (int g = 0; g < NG; g++)
        v[g] = xn[g] * exc[g] / fmaxf(sqrtf(e2[g]), 1e-8f);
    reduce8(v, scr, out8, lane, warp, j);
    if (j < NG) g_lbl[s * NG + j] = fmaxf(30.f * out8[j], 1e-6f);

    // store normalized rows k-major: each thread writes 8 contiguous floats (one 32B sector)
    #pragma unroll
    for (int g = 0; g < NG; g++) g_xnT[j * NR + s * NG + g] = xn[g];

    if (s == 0 && j == 0) out[0] = 0.f;   // zero the accumulator (d_out is poisoned)
}

// ---------------------------------------------------------------------------
// Kernel 2: fused similarity GEMM + online log-softmax + NLL accumulation.
// Grid: 256 blocks of 256 threads; block = 64 rows x all 2048 centroids.
// acc packed 2-wide along N via fma.rn.f32x2.
// ---------------------------------------------------------------------------
__global__ void loss_kernel(float* __restrict__ out) {
    extern __shared__ float sm[];
    float* As = sm;              // [ND][BM] = 8192 floats
    float* Bs = sm + ND * BM;    // [ND][BN] = 8192 floats

    const int tid  = threadIdx.x;
    const int ty   = tid >> 4;     // 0..15 -> 4 rows each
    const int tx   = tid & 15;     // 0..15 -> 4 cols each
    const int row0 = blockIdx.x * BM;

    // load A tile once (k-major, fully coalesced, linear smem store)
    #pragma unroll
    for (int it = 0; it < (ND * BM) / 256; it++) {
        int idx = it * 256 + tid;
        int r = idx & (BM - 1);
        int k = idx >> 6;
        As[idx] = g_xnT[k * NR + row0 + r];
    }

    float lblv[4], sums[4];
    int   srow[4];
    #pragma unroll
    for (int i = 0; i < 4; i++) {
        int row = row0 + 4 * ty + i;
        lblv[i] = g_lbl[row];
        srow[i] = row >> 3;         // owning speaker (diagonal column)
        sums[i] = 0.f;
    }

    const float4*     A4 = (const float4*)As;
    const ulonglong2* B2 = (const ulonglong2*)Bs;

    for (int t0 = 0; t0 < NS; t0 += BN) {
        __syncthreads();
        #pragma unroll
        for (int it = 0; it < (ND * BN) / 256; it++) {
            int idx = it * 256 + tid;
            int c = idx & (BN - 1);
            int k = idx >> 6;
            Bs[idx] = g_centT[k * NS + t0 + c];
        }
        __syncthreads();

        ull acc[4][2];
        #pragma unroll
        for (int i = 0; i < 4; i++) { acc[i][0] = 0ull; acc[i][1] = 0ull; }

        #pragma unroll 8
        for (int k = 0; k < ND; k++) {
            float4     av = A4[k * (BM / 4) + ty];
            ulonglong2 bb = B2[k * (BN / 4) + tx];
            ull a0 = pack_dup(av.x), a1 = pack_dup(av.y);
            ull a2 = pack_dup(av.z), a3 = pack_dup(av.w);
            acc[0][0] = fma2(a0, bb.x, acc[0][0]); acc[0][1] = fma2(a0, bb.y, acc[0][1]);
            acc[1][0] = fma2(a1, bb.x, acc[1][0]); acc[1][1] = fma2(a1, bb.y, acc[1][1]);
            acc[2][0] = fma2(a2, bb.x, acc[2][0]); acc[2][1] = fma2(a2, bb.y, acc[2][1]);
            acc[3][0] = fma2(a3, bb.x, acc[3][0]); acc[3][1] = fma2(a3, bb.y, acc[3][1]);
        }

        // epilogue: clamp / diagonal replacement / online sum-exp (logits <= 30, no max pass)
        #pragma unroll
        for (int i = 0; i < 4; i++) {
            #pragma unroll
            for (int jj = 0; jj < 2; jj++) {
                float2 f = unpack2(acc[i][jj]);
                int c0 = t0 + 4 * tx + 2 * jj;
                float v0 = (c0     == srow[i]) ? lblv[i] : fmaxf(f.x, 1e-6f);
                float v1 = (c0 + 1 == srow[i]) ? lblv[i] : fmaxf(f.y, 1e-6f);
                sums[i] += __expf(v0 - 30.f) + __expf(v1 - 30.f);
            }
        }
    }

    // reduce per-row partial sums across the 16 tx lanes (xor offsets stay inside half-warp)
    float local = 0.f;
    #pragma unroll
    for (int i = 0; i < 4; i++) {
        float ssum = sums[i];
        #pragma unroll
        for (int off = 8; off > 0; off >>= 1)
            ssum += __shfl_xor_sync(0xffffffffu, ssum, off);
        if (tx == 0) local += 30.f + logf(ssum) - lblv[i];   // lse - label_logit
    }

    __syncthreads();
    if (tx == 0) sm[ty] = local;
    __syncthreads();
    if (tid == 0) {
        float tot = 0.f;
        #pragma unroll
        for (int q = 0; q < 16; q++) tot += sm[q];
        atomicAdd(out, tot * (1.f / (float)NR));
    }
}

// ---------------------------------------------------------------------------
extern "C" void kernel_launch(void* const* d_in, const int* in_sizes, int n_in,
                              void* d_out, int out_size) {
    const float* x = (const float*)d_in[0];
    float* out = (float*)d_out;

    prep_kernel<<<NS, 128>>>(x, out);

    cudaFuncSetAttribute(loss_kernel, cudaFuncAttributeMaxDynamicSharedMemorySize, 65536);
    loss_kernel<<<NR / BM, 256, 65536>>>(out);
}

// round 2
// speedup vs baseline: 1.0061x; 1.0061x over previous
#include <cuda_runtime.h>
#include <math.h>

#define NS 2048      // speakers
#define NG 8         // utts per speaker
#define ND 128       // embed dim
#define NR (NS*NG)   // 16384 rows
#define BM 64
#define BN 64

// Scratch (device globals; no allocation allowed)
__device__ float g_xnT[ND * NR];    // [k][r]  normalized x, k-major
__device__ float g_centT[ND * NS];  // [k][t]  normalized centroids * 30, k-major
__device__ float g_lbl[NR];         // label logit per row = max(30*cos_exc, 1e-6)

// ---------------------------------------------------------------------------
// f32x2 helpers
// ---------------------------------------------------------------------------
typedef unsigned long long ull;

__device__ __forceinline__ ull pack_dup(float v) {
    ull r; asm("mov.b64 %0, {%1, %1};" : "=l"(r) : "f"(v)); return r;
}
__device__ __forceinline__ ull fma2(ull a, ull b, ull c) {
    ull d; asm("fma.rn.f32x2 %0, %1, %2, %3;" : "=l"(d) : "l"(a), "l"(b), "l"(c)); return d;
}
__device__ __forceinline__ float2 unpack2(ull v) {
    float2 f; asm("mov.b64 {%0, %1}, %2;" : "=f"(f.x), "=f"(f.y) : "l"(v)); return f;
}

// ---------------------------------------------------------------------------
// Kernel 1: per-speaker prep. One block (128 threads) per speaker.
// Thread j owns dimension j for all 8 utterances.
// ---------------------------------------------------------------------------
__device__ __forceinline__ void reduce8(const float v[NG], float (*scr)[4],
                                        float* out8, int lane, int warp, int tid) {
    #pragma unroll
    for (int g = 0; g < NG; g++) {
        float r = v[g];
        #pragma unroll
        for (int off = 16; off > 0; off >>= 1)
            r += __shfl_xor_sync(0xffffffffu, r, off);
        if (lane == 0) scr[g][warp] = r;
    }
    __syncthreads();
    if (tid < NG) out8[tid] = scr[tid][0] + scr[tid][1] + scr[tid][2] + scr[tid][3];
    __syncthreads();
}

__global__ void prep_kernel(const float* __restrict__ x, float* __restrict__ out) {
    __shared__ float scr[NG][4];
    __shared__ float out8[NG];
    __shared__ float cnorm2;

    const int s    = blockIdx.x;
    const int j    = threadIdx.x;       // 0..127
    const int lane = j & 31;
    const int warp = j >> 5;

    float xg[NG];
    #pragma unroll
    for (int g = 0; g < NG; g++) xg[g] = x[(s * NG + g) * ND + j];

    // row norms
    float v[NG];
    #pragma unroll
    for (int g = 0; g < NG; g++) v[g] = xg[g] * xg[g];
    reduce8(v, scr, out8, lane, warp, j);
    float xn[NG];
    float sum = 0.f;
    #pragma unroll
    for (int g = 0; g < NG; g++) {
        float nrm = fmaxf(sqrtf(out8[g]), 1e-12f);
        xn[g] = xg[g] / nrm;
        sum += xn[g];
    }

    // centroid (mean of normalized rows), then normalize + pre-scale by 30
    float cent = sum * 0.125f;
    {
        float c2 = cent * cent;
        #pragma unroll
        for (int off = 16; off > 0; off >>= 1)
            c2 += __shfl_xor_sync(0xffffffffu, c2, off);
        if (lane == 0) scr[0][warp] = c2;
        __syncthreads();
        if (j == 0) cnorm2 = scr[0][0] + scr[0][1] + scr[0][2] + scr[0][3];
        __syncthreads();
    }
    g_centT[j * NS + s] = 30.f * cent / fmaxf(sqrtf(cnorm2), 1e-8f);

    // exclusive centroids
    float exc[NG];
    #pragma unroll
    for (int g = 0; g < NG; g++) {
        exc[g] = (sum - xn[g]) * (1.0f / 7.0f);
        v[g] = exc[g] * exc[g];
    }
    reduce8(v, scr, out8, lane, warp, j);
    float e2[NG];
    #pragma unroll
    for (int g = 0; g < NG; g++) e2[g] = out8[g];

    // cosine vs exclusive centroid
    #pragma unroll
    for (int g = 0; g < NG; g++)
        v[g] = xn[g] * exc[g] / fmaxf(sqrtf(e2[g]), 1e-8f);
    reduce8(v, scr, out8, lane, warp, j);
    if (j < NG) g_lbl[s * NG + j] = fmaxf(30.f * out8[j], 1e-6f);

    // store normalized rows k-major: each thread writes 8 contiguous floats (one 32B sector)
    #pragma unroll
    for (int g = 0; g < NG; g++) g_xnT[j * NR + s * NG + g] = xn[g];

    if (s == 0 && j == 0) out[0] = 0.f;   // zero the accumulator (d_out is poisoned)
}

// ---------------------------------------------------------------------------
// Kernel 2: fused similarity GEMM + online log-softmax + NLL accumulation.
// Grid: 256 blocks of 256 threads; block = 64 rows x all 2048 centroids.
// acc packed 2-wide along N via fma.rn.f32x2.
// ---------------------------------------------------------------------------
__global__ void loss_kernel(float* __restrict__ out) {
    extern __shared__ float sm[];
    float* As = sm;              // [ND][BM] = 8192 floats
    float* Bs = sm + ND * BM;    // [ND][BN] = 8192 floats

    const int tid  = threadIdx.x;
    const int ty   = tid >> 4;     // 0..15 -> 4 rows each
    const int tx   = tid & 15;     // 0..15 -> 4 cols each
    const int row0 = blockIdx.x * BM;

    // load A tile once (k-major, fully coalesced, linear smem store)
    #pragma unroll
    for (int it = 0; it < (ND * BM) / 256; it++) {
        int idx = it * 256 + tid;
        int r = idx & (BM - 1);
        int k = idx >> 6;
        As[idx] = g_xnT[k * NR + row0 + r];
    }

    float lblv[4], sums[4];
    int   srow[4];
    #pragma unroll
    for (int i = 0; i < 4; i++) {
        int row = row0 + 4 * ty + i;
        lblv[i] = g_lbl[row];
        srow[i] = row >> 3;         // owning speaker (diagonal column)
        sums[i] = 0.f;
    }

    const float4*     A4 = (const float4*)As;
    const ulonglong2* B2 = (const ulonglong2*)Bs;

    for (int t0 = 0; t0 < NS; t0 += BN) {
        __syncthreads();
        #pragma unroll
        for (int it = 0; it < (ND * BN) / 256; it++) {
            int idx = it * 256 + tid;
            int c = idx & (BN - 1);
            int k = idx >> 6;
            Bs[idx] = g_centT[k * NS + t0 + c];
        }
        __syncthreads();

        ull acc[4][2];
        #pragma unroll
        for (int i = 0; i < 4; i++) { acc[i][0] = 0ull; acc[i][1] = 0ull; }

        #pragma unroll 8
        for (int k = 0; k < ND; k++) {
            float4     av = A4[k * (BM / 4) + ty];
            ulonglong2 bb = B2[k * (BN / 4) + tx];
            ull a0 = pack_dup(av.x), a1 = pack_dup(av.y);
            ull a2 = pack_dup(av.z), a3 = pack_dup(av.w);
            acc[0][0] = fma2(a0, bb.x, acc[0][0]); acc[0][1] = fma2(a0, bb.y, acc[0][1]);
            acc[1][0] = fma2(a1, bb.x, acc[1][0]); acc[1][1] = fma2(a1, bb.y, acc[1][1]);
            acc[2][0] = fma2(a2, bb.x, acc[2][0]); acc[2][1] = fma2(a2, bb.y, acc[2][1]);
            acc[3][0] = fma2(a3, bb.x, acc[3][0]); acc[3][1] = fma2(a3, bb.y, acc[3][1]);
        }

        // epilogue: clamp / diagonal replacement / online sum-exp (logits <= 30, no max pass)
        #pragma unroll
        for (int i = 0; i < 4; i++) {
            #pragma unroll
            for (int jj = 0; jj < 2; jj++) {
                float2 f = unpack2(acc[i][jj]);
                int c0 = t0 + 4 * tx + 2 * jj;
                float v0 = (c0     == srow[i]) ? lblv[i] : fmaxf(f.x, 1e-6f);
                float v1 = (c0 + 1 == srow[i]) ? lblv[i] : fmaxf(f.y, 1e-6f);
                sums[i] += __expf(v0 - 30.f) + __expf(v1 - 30.f);
            }
        }
    }

    // reduce per-row partial sums across the 16 tx lanes (xor offsets stay inside half-warp)
    float local = 0.f;
    #pragma unroll
    for (int i = 0; i < 4; i++) {
        float ssum = sums[i];
        #pragma unroll
        for (int off = 8; off > 0; off >>= 1)
            ssum += __shfl_xor_sync(0xffffffffu, ssum, off);
        if (tx == 0) local += 30.f + logf(ssum) - lblv[i];   // lse - label_logit
    }

    __syncthreads();
    if (tx == 0) sm[ty] = local;
    __syncthreads();
    if (tid == 0) {
        float tot = 0.f;
        #pragma unroll
        for (int q = 0; q < 16; q++) tot += sm[q];
        atomicAdd(out, tot * (1.f / (float)NR));
    }
}

// ---------------------------------------------------------------------------
extern "C" void kernel_launch(void* const* d_in, const int* in_sizes, int n_in,
                              void* d_out, int out_size) {
    const float* x = (const float*)d_in[0];
    float* out = (float*)d_out;

    prep_kernel<<<NS, 128>>>(x, out);

    cudaFuncSetAttribute(loss_kernel, cudaFuncAttributeMaxDynamicSharedMemorySize, 65536);
    loss_kernel<<<NR / BM, 256, 65536>>>(out);
}

// round 4
// speedup vs baseline: 2.3723x; 2.3580x over previous
#include <cuda_runtime.h>
#include <cuda_fp16.h>
#include <cstdint>
#include <math.h>

#define NS 2048      // speakers
#define NG 8         // utts per speaker
#define ND 128       // embed dim
#define NR (NS*NG)   // 16384 rows
#define KC 384       // K-concat: [Ah|Ah|Al] x [Bh|Bl|Bh]
#define NCH (KC/8)   // 48 16-byte chunks per row
#define BM 128
#define BN 64
#define NTILES (NS/BN)   // 32

// ---------------------------------------------------------------------------
// device globals (no allocation allowed)
// ---------------------------------------------------------------------------
__device__ float g_lbl[NR];
__device__ __align__(16) __half2 g_A2[NR * (KC/2)];   // [row][192] pairs
__device__ __align__(16) __half2 g_B2[NS * (KC/2)];   // [spk][192] pairs

// ---------------------------------------------------------------------------
// PTX helpers (all plain sm_80/sm_90 — safe for compute_103)
// ---------------------------------------------------------------------------
__device__ __forceinline__ uint32_t smem_u32(const void* p) {
    uint32_t a;
    asm("{ .reg .u64 t; cvta.to.shared.u64 t, %1; cvt.u32.u64 %0, t; }" : "=r"(a) : "l"(p));
    return a;
}
#define CP16(dst32, gptr) \
    asm volatile("cp.async.cg.shared.global [%0], [%1], 16;" \
        :: "r"(dst32), "l"(__cvta_generic_to_global(gptr)) : "memory")
#define CP_COMMIT() asm volatile("cp.async.commit_group;" ::: "memory")
#define CP_WAIT0()  asm volatile("cp.async.wait_group 0;" ::: "memory")
#define CP_WAIT1()  asm volatile("cp.async.wait_group 1;" ::: "memory")

__device__ __forceinline__ void ldsm4(unsigned r[4], uint32_t addr) {
    asm volatile("ldmatrix.sync.aligned.m8n8.x4.shared.b16 {%0,%1,%2,%3}, [%4];"
        : "=r"(r[0]), "=r"(r[1]), "=r"(r[2]), "=r"(r[3]) : "r"(addr));
}
__device__ __forceinline__ void mma16816(float d[4], const unsigned a[4],
                                         unsigned b0, unsigned b1) {
    asm volatile("mma.sync.aligned.m16n8k16.row.col.f32.f16.f16.f32 "
        "{%0,%1,%2,%3}, {%4,%5,%6,%7}, {%8,%9}, {%0,%1,%2,%3};"
        : "+f"(d[0]), "+f"(d[1]), "+f"(d[2]), "+f"(d[3])
        : "r"(a[0]), "r"(a[1]), "r"(a[2]), "r"(a[3]), "r"(b0), "r"(b1));
}

// ---------------------------------------------------------------------------
// Kernel 1: per-speaker prep. One block (128 threads) per speaker.
// Emits g_lbl, g_A2 = [Ah|Ah|Al] fp16 pairs, g_B2 = [Bh|Bl|Bh].
// ---------------------------------------------------------------------------
__device__ __forceinline__ void reduce8(const float v[NG], float (*scr)[4],
                                        float* out8, int lane, int warp, int tid) {
    #pragma unroll
    for (int g = 0; g < NG; g++) {
        float r = v[g];
        #pragma unroll
        for (int off = 16; off > 0; off >>= 1)
            r += __shfl_xor_sync(0xffffffffu, r, off);
        if (lane == 0) scr[g][warp] = r;
    }
    __syncthreads();
    if (tid < NG) out8[tid] = scr[tid][0] + scr[tid][1] + scr[tid][2] + scr[tid][3];
    __syncthreads();
}

__device__ __forceinline__ __half2 hi_pair(float a, float b) {
    return __halves2half2(__float2half_rn(a), __float2half_rn(b));
}
__device__ __forceinline__ __half2 lo_pair(float a, float b) {
    float ra = a - __half2float(__float2half_rn(a));
    float rb = b - __half2float(__float2half_rn(b));
    return __halves2half2(__float2half_rn(ra), __float2half_rn(rb));
}

__global__ void prep_kernel(const float* __restrict__ x, float* __restrict__ out) {
    __shared__ float scr[NG][4];
    __shared__ float out8[NG];
    __shared__ float cnorm2;
    __shared__ float xs[NG][ND];
    __shared__ float cs[ND];

    const int s    = blockIdx.x;
    const int j    = threadIdx.x;       // 0..127
    const int lane = j & 31;
    const int warp = j >> 5;

    float xg[NG];
    #pragma unroll
    for (int g = 0; g < NG; g++) xg[g] = x[(s * NG + g) * ND + j];

    // row norms
    float v[NG];
    #pragma unroll
    for (int g = 0; g < NG; g++) v[g] = xg[g] * xg[g];
    reduce8(v, scr, out8, lane, warp, j);
    float xn[NG];
    float sum = 0.f;
    #pragma unroll
    for (int g = 0; g < NG; g++) {
        float nrm = fmaxf(sqrtf(out8[g]), 1e-12f);
        xn[g] = xg[g] / nrm;
        sum += xn[g];
    }

    // centroid -> normalized, pre-scaled by 30
    float cent = sum * 0.125f;
    {
        float c2 = cent * cent;
        #pragma unroll
        for (int off = 16; off > 0; off >>= 1)
            c2 += __shfl_xor_sync(0xffffffffu, c2, off);
        if (lane == 0) scr[0][warp] = c2;
        __syncthreads();
        if (j == 0) cnorm2 = scr[0][0] + scr[0][1] + scr[0][2] + scr[0][3];
        __syncthreads();
    }
    float centv = 30.f * cent / fmaxf(sqrtf(cnorm2), 1e-8f);

    // exclusive centroids + cosine
    float exc[NG];
    #pragma unroll
    for (int g = 0; g < NG; g++) {
        exc[g] = (sum - xn[g]) * (1.0f / 7.0f);
        v[g] = exc[g] * exc[g];
    }
    reduce8(v, scr, out8, lane, warp, j);
    float e2[NG];
    #pragma unroll
    for (int g = 0; g < NG; g++) e2[g] = out8[g];
    #pragma unroll
    for (int g = 0; g < NG; g++)
        v[g] = xn[g] * exc[g] / fmaxf(sqrtf(e2[g]), 1e-8f);
    reduce8(v, scr, out8, lane, warp, j);
    if (j < NG) g_lbl[s * NG + j] = fmaxf(30.f * out8[j], 1e-6f);

    // stage to smem for pair packing
    #pragma unroll
    for (int g = 0; g < NG; g++) xs[g][j] = xn[g];
    cs[j] = centv;
    __syncthreads();

    // A': [Ah(128) | Ah(128) | Al(128)] as fp16 pairs
    const int abase = s * NG * (KC/2);
    #pragma unroll
    for (int it = 0; it < (NG * (KC/2)) / 128; it++) {   // 12 iters
        int idx = it * 128 + j;
        int r  = idx / (KC/2);
        int p  = idx % (KC/2);
        int pm = p & 63, blk = p >> 6;
        float v0 = xs[r][2*pm], v1 = xs[r][2*pm+1];
        g_A2[abase + idx] = (blk < 2) ? hi_pair(v0, v1) : lo_pair(v0, v1);
    }

    // B': [Bh | Bl | Bh]
    #pragma unroll
    for (int p = j; p < (KC/2); p += 128) {
        int pm = p & 63, blk = p >> 6;
        float v0 = cs[2*pm], v1 = cs[2*pm+1];
        g_B2[s * (KC/2) + p] = (blk == 1) ? lo_pair(v0, v1) : hi_pair(v0, v1);
    }

    if (s == 0 && j == 0) out[0] = 0.f;   // zero accumulator (d_out is poisoned)
}

// ---------------------------------------------------------------------------
// Kernel 2: HMMA GEMM (fp16x3) + fused online log-softmax.
// 128 CTAs x 128 threads. CTA = 128 rows x all 2048 centroids.
// A (128x384 fp16) smem-resident; B in 64-col double-buffered tiles (cp.async).
// Warp grid 2m x 2n, warp tile 64x32.
// ---------------------------------------------------------------------------
#define SM_A     0
#define SM_B0    98304
#define SM_B1    147456
#define SM_TOTAL 196608

__global__ void __launch_bounds__(128, 1) gemm_kernel(float* __restrict__ out) {
    extern __shared__ char smem[];
    __shared__ float zbuf[BM][2];
    __shared__ float cbuf[BM][2];
    __shared__ float red[4];

    const uint32_t sb = smem_u32(smem);
    const int tid  = threadIdx.x;
    const int lane = tid & 31;
    const int wid  = tid >> 5;
    const int wm   = wid >> 1;       // 0..1
    const int wn   = wid & 1;        // 0..1
    const int br0  = blockIdx.x * BM;
    const int td   = blockIdx.x >> 2;   // tile holding all diagonal cols

    const char* gA = (const char*)g_A2;
    const char* gB = (const char*)g_B2;

    // ---- prologue: A tile (all 48 chunks x 128 rows) + B tile 0 ----
    #pragma unroll
    for (int ii = 0; ii < (BM * NCH) / 128; ii++) {     // 48 iters
        int idx = ii * 128 + tid;
        int c = idx % NCH, r = idx / NCH;
        CP16(sb + SM_A + r * 768 + ((c ^ (r & 7)) << 4),
             gA + (size_t)(br0 + r) * 768 + c * 16);
    }
    #pragma unroll
    for (int ii = 0; ii < (BN * NCH) / 128; ii++) {     // 24 iters
        int idx = ii * 128 + tid;
        int c = idx % NCH, n = idx / NCH;
        CP16(sb + SM_B0 + n * 768 + ((c ^ (n & 7)) << 4),
             gB + (size_t)n * 768 + c * 16);
    }
    CP_COMMIT();

    // ---- per-thread fragment address bases ----
    uint32_t aBase[4], aS[4];
    #pragma unroll
    for (int mi = 0; mi < 4; mi++) {
        int row = wm * 64 + mi * 16 + (lane & 15);
        aBase[mi] = sb + SM_A + row * 768;
        aS[mi] = row & 7;
    }
    const uint32_t cbA = (lane >> 4);          // 0/1 -> k-octet within k16
    uint32_t bOff[2], bS[2];
    #pragma unroll
    for (int j2 = 0; j2 < 2; j2++) {
        int n = wn * 32 + j2 * 16 + ((lane >> 4) & 1) * 8 + (lane & 7);
        bOff[j2] = n * 768;
        bS[j2] = n & 7;
    }
    const uint32_t cbB = (lane >> 3) & 1;

    // row slots: slot = mi*2 + h, row = wm*64 + mi*16 + h*8 + lane/4
    int rl[8], dc[8];
    float zsum[8], zcorr[8];
    #pragma unroll
    for (int sl = 0; sl < 8; sl++) {
        int mi = sl >> 1, h = sl & 1;
        rl[sl] = wm * 64 + mi * 16 + h * 8 + (lane >> 2);
        dc[sl] = (br0 + rl[sl]) >> 3;
        zsum[sl] = 0.f; zcorr[sl] = 0.f;
    }

    const uint32_t bufB[2] = { sb + SM_B0, sb + SM_B1 };

    for (int t = 0; t < NTILES; t++) {
        // prefetch next B tile into the other buffer
        if (t + 1 < NTILES) {
            const uint32_t bb = bufB[(t + 1) & 1];
            #pragma unroll
            for (int ii = 0; ii < (BN * NCH) / 128; ii++) {
                int idx = ii * 128 + tid;
                int c = idx % NCH, n = idx / NCH;
                CP16(bb + n * 768 + ((c ^ (n & 7)) << 4),
                     gB + (size_t)((t + 1) * BN + n) * 768 + c * 16);
            }
            CP_COMMIT();
            CP_WAIT1();
        } else {
            CP_WAIT0();
        }
        __syncthreads();

        const uint32_t bcur = bufB[t & 1];
        float acc[4][4][4];
        #pragma unroll
        for (int mi = 0; mi < 4; mi++)
            #pragma unroll
            for (int nj = 0; nj < 4; nj++)
                #pragma unroll
                for (int q = 0; q < 4; q++) acc[mi][nj][q] = 0.f;

        #pragma unroll
        for (int ks = 0; ks < KC / 16; ks++) {          // 24 steps
            const uint32_t c2 = 2u * ks;
            unsigned af[4][4], bf[2][4];
            #pragma unroll
            for (int mi = 0; mi < 4; mi++)
                ldsm4(af[mi], aBase[mi] + (((c2 | cbA) ^ aS[mi]) << 4));
            #pragma unroll
            for (int j2 = 0; j2 < 2; j2++)
                ldsm4(bf[j2], bcur + bOff[j2] + (((c2 | cbB) ^ bS[j2]) << 4));
            #pragma unroll
            for (int mi = 0; mi < 4; mi++)
                #pragma unroll
                for (int nj = 0; nj < 4; nj++)
                    mma16816(acc[mi][nj], af[mi],
                             bf[nj >> 1][(nj & 1) * 2], bf[nj >> 1][(nj & 1) * 2 + 1]);
        }

        // fused epilogue: clamp + exp + online Z (logits <= 30 so no max pass)
        if (t == td) {
            #pragma unroll
            for (int mi = 0; mi < 4; mi++)
                #pragma unroll
                for (int nj = 0; nj < 4; nj++) {
                    int cb = t * BN + wn * 32 + nj * 8 + (lane & 3) * 2;
                    float e0 = __expf(fmaxf(acc[mi][nj][0], 1e-6f) - 30.f);
                    float e1 = __expf(fmaxf(acc[mi][nj][1], 1e-6f) - 30.f);
                    float e2 = __expf(fmaxf(acc[mi][nj][2], 1e-6f) - 30.f);
                    float e3 = __expf(fmaxf(acc[mi][nj][3], 1e-6f) - 30.f);
                    zsum[mi*2]   += e0 + e1;
                    zsum[mi*2+1] += e2 + e3;
                    if (cb     == dc[mi*2])   zcorr[mi*2]   += e0;
                    if (cb + 1 == dc[mi*2])   zcorr[mi*2]   += e1;
                    if (cb     == dc[mi*2+1]) zcorr[mi*2+1] += e2;
                    if (cb + 1 == dc[mi*2+1]) zcorr[mi*2+1] += e3;
                }
        } else {
            #pragma unroll
            for (int mi = 0; mi < 4; mi++)
                #pragma unroll
                for (int nj = 0; nj < 4; nj++) {
                    float e0 = __expf(fmaxf(acc[mi][nj][0], 1e-6f) - 30.f);
                    float e1 = __expf(fmaxf(acc[mi][nj][1], 1e-6f) - 30.f);
                    float e2 = __expf(fmaxf(acc[mi][nj][2], 1e-6f) - 30.f);
                    float e3 = __expf(fmaxf(acc[mi][nj][3], 1e-6f) - 30.f);
                    zsum[mi*2]   += e0 + e1;
                    zsum[mi*2+1] += e2 + e3;
                }
        }
        __syncthreads();
    }

    // reduce zsum/zcorr across the 4 lanes of each quad (same row)
    #pragma unroll
    for (int sl = 0; sl < 8; sl++) {
        float z = zsum[sl], c = zcorr[sl];
        z += __shfl_xor_sync(0xffffffffu, z, 1);
        z += __shfl_xor_sync(0xffffffffu, z, 2);
        c += __shfl_xor_sync(0xffffffffu, c, 1);
        c += __shfl_xor_sync(0xffffffffu, c, 2);
        if ((lane & 3) == 0) { zbuf[rl[sl]][wn] = z; cbuf[rl[sl]][wn] = c; }
    }
    __syncthreads();

    // per-row loss + block reduce + single atomicAdd
    int row = br0 + tid;
    float lbl = g_lbl[row];
    float Z = zbuf[tid][0] + zbuf[tid][1] - cbuf[tid][0] - cbuf[tid][1]
              + __expf(lbl - 30.f);
    float loss = 30.f + logf(Z) - lbl;
    #pragma unroll
    for (int off = 16; off > 0; off >>= 1)
        loss += __shfl_xor_sync(0xffffffffu, loss, off);
    if (lane == 0) red[wid] = loss;
    __syncthreads();
    if (tid == 0)
        atomicAdd(out, (red[0] + red[1] + red[2] + red[3]) * (1.f / (float)NR));
}

// ---------------------------------------------------------------------------
extern "C" void kernel_launch(void* const* d_in, const int* in_sizes, int n_in,
                              void* d_out, int out_size) {
    const float* x = (const float*)d_in[0];
    float* out = (float*)d_out;

    prep_kernel<<<NS, 128>>>(x, out);

    cudaFuncSetAttribute(gemm_kernel, cudaFuncAttributeMaxDynamicSharedMemorySize, SM_TOTAL);
    gemm_kernel<<<NR / BM, 128, SM_TOTAL>>>(out);
}

// round 5
// speedup vs baseline: 2.5782x; 1.0868x over previous
#include <cuda_runtime.h>
#include <cuda_fp16.h>
#include <cstdint>
#include <math.h>

#define NS 2048      // speakers
#define NG 8         // utts per speaker
#define ND 128       // embed dim
#define NR (NS*NG)   // 16384 rows
#define KC 384       // K-concat: [Ah|Ah|Al] x [Bh|Bl|Bh]
#define NCH (KC/8)   // 48 16-byte chunks per row
#define BM 128
#define BN 64
#define NTILES (NS/BN)   // 32
#define NT 256           // threads per CTA

// ---------------------------------------------------------------------------
// device globals (no allocation allowed)
// ---------------------------------------------------------------------------
__device__ float g_lbl[NR];
__device__ __align__(16) __half2 g_A2[NR * (KC/2)];   // [row][192] pairs
__device__ __align__(16) __half2 g_B2[NS * (KC/2)];   // [spk][192] pairs

// ---------------------------------------------------------------------------
// PTX helpers (plain sm_80/90 — safe for compute_103)
// ---------------------------------------------------------------------------
__device__ __forceinline__ uint32_t smem_u32(const void* p) {
    uint32_t a;
    asm("{ .reg .u64 t; cvta.to.shared.u64 t, %1; cvt.u32.u64 %0, t; }" : "=r"(a) : "l"(p));
    return a;
}
#define CP16(dst32, gptr) \
    asm volatile("cp.async.cg.shared.global [%0], [%1], 16;" \
        :: "r"(dst32), "l"(__cvta_generic_to_global(gptr)) : "memory")
#define CP_COMMIT() asm volatile("cp.async.commit_group;" ::: "memory")
#define CP_WAIT0()  asm volatile("cp.async.wait_group 0;" ::: "memory")
#define CP_WAIT1()  asm volatile("cp.async.wait_group 1;" ::: "memory")

__device__ __forceinline__ void ldsm4(unsigned r[4], uint32_t addr) {
    asm volatile("ldmatrix.sync.aligned.m8n8.x4.shared.b16 {%0,%1,%2,%3}, [%4];"
        : "=r"(r[0]), "=r"(r[1]), "=r"(r[2]), "=r"(r[3]) : "r"(addr));
}
__device__ __forceinline__ void mma16816(float d[4], const unsigned a[4],
                                         unsigned b0, unsigned b1) {
    asm volatile("mma.sync.aligned.m16n8k16.row.col.f32.f16.f16.f32 "
        "{%0,%1,%2,%3}, {%4,%5,%6,%7}, {%8,%9}, {%0,%1,%2,%3};"
        : "+f"(d[0]), "+f"(d[1]), "+f"(d[2]), "+f"(d[3])
        : "r"(a[0]), "r"(a[1]), "r"(a[2]), "r"(a[3]), "r"(b0), "r"(b1));
}

// ---------------------------------------------------------------------------
// Kernel 1: per-speaker prep (unchanged from R4 — it's off the critical path)
// ---------------------------------------------------------------------------
__device__ __forceinline__ void reduce8(const float v[NG], float (*scr)[4],
                                        float* out8, int lane, int warp, int tid) {
    #pragma unroll
    for (int g = 0; g < NG; g++) {
        float r = v[g];
        #pragma unroll
        for (int off = 16; off > 0; off >>= 1)
            r += __shfl_xor_sync(0xffffffffu, r, off);
        if (lane == 0) scr[g][warp] = r;
    }
    __syncthreads();
    if (tid < NG) out8[tid] = scr[tid][0] + scr[tid][1] + scr[tid][2] + scr[tid][3];
    __syncthreads();
}

__device__ __forceinline__ __half2 hi_pair(float a, float b) {
    return __halves2half2(__float2half_rn(a), __float2half_rn(b));
}
__device__ __forceinline__ __half2 lo_pair(float a, float b) {
    float ra = a - __half2float(__float2half_rn(a));
    float rb = b - __half2float(__float2half_rn(b));
    return __halves2half2(__float2half_rn(ra), __float2half_rn(rb));
}

__global__ void prep_kernel(const float* __restrict__ x, float* __restrict__ out) {
    __shared__ float scr[NG][4];
    __shared__ float out8[NG];
    __shared__ float cnorm2;
    __shared__ float xs[NG][ND];
    __shared__ float cs[ND];

    const int s    = blockIdx.x;
    const int j    = threadIdx.x;       // 0..127
    const int lane = j & 31;
    const int warp = j >> 5;

    float xg[NG];
    #pragma unroll
    for (int g = 0; g < NG; g++) xg[g] = x[(s * NG + g) * ND + j];

    float v[NG];
    #pragma unroll
    for (int g = 0; g < NG; g++) v[g] = xg[g] * xg[g];
    reduce8(v, scr, out8, lane, warp, j);
    float xn[NG];
    float sum = 0.f;
    #pragma unroll
    for (int g = 0; g < NG; g++) {
        float nrm = fmaxf(sqrtf(out8[g]), 1e-12f);
        xn[g] = xg[g] / nrm;
        sum += xn[g];
    }

    float cent = sum * 0.125f;
    {
        float c2 = cent * cent;
        #pragma unroll
        for (int off = 16; off > 0; off >>= 1)
            c2 += __shfl_xor_sync(0xffffffffu, c2, off);
        if (lane == 0) scr[0][warp] = c2;
        __syncthreads();
        if (j == 0) cnorm2 = scr[0][0] + scr[0][1] + scr[0][2] + scr[0][3];
        __syncthreads();
    }
    float centv = 30.f * cent / fmaxf(sqrtf(cnorm2), 1e-8f);

    float exc[NG];
    #pragma unroll
    for (int g = 0; g < NG; g++) {
        exc[g] = (sum - xn[g]) * (1.0f / 7.0f);
        v[g] = exc[g] * exc[g];
    }
    reduce8(v, scr, out8, lane, warp, j);
    float e2[NG];
    #pragma unroll
    for (int g = 0; g < NG; g++) e2[g] = out8[g];
    #pragma unroll
    for (int g = 0; g < NG; g++)
        v[g] = xn[g] * exc[g] / fmaxf(sqrtf(e2[g]), 1e-8f);
    reduce8(v, scr, out8, lane, warp, j);
    if (j < NG) g_lbl[s * NG + j] = fmaxf(30.f * out8[j], 1e-6f);

    #pragma unroll
    for (int g = 0; g < NG; g++) xs[g][j] = xn[g];
    cs[j] = centv;
    __syncthreads();

    // A': [Ah | Ah | Al] fp16 pairs
    const int abase = s * NG * (KC/2);
    #pragma unroll
    for (int it = 0; it < (NG * (KC/2)) / 128; it++) {
        int idx = it * 128 + j;
        int r  = idx / (KC/2);
        int p  = idx % (KC/2);
        int pm = p & 63, blk = p >> 6;
        float v0 = xs[r][2*pm], v1 = xs[r][2*pm+1];
        g_A2[abase + idx] = (blk < 2) ? hi_pair(v0, v1) : lo_pair(v0, v1);
    }

    // B': [Bh | Bl | Bh]
    #pragma unroll
    for (int p = j; p < (KC/2); p += 128) {
        int pm = p & 63, blk = p >> 6;
        float v0 = cs[2*pm], v1 = cs[2*pm+1];
        g_B2[s * (KC/2) + p] = (blk == 1) ? lo_pair(v0, v1) : hi_pair(v0, v1);
    }

    if (s == 0 && j == 0) out[0] = 0.f;   // zero accumulator (d_out is poisoned)
}

// ---------------------------------------------------------------------------
// Kernel 2: HMMA GEMM (fp16x3) + fused online log-softmax.
// 128 CTAs x 256 threads (8 warps = 2/SMSP). CTA = 128 rows x all 2048 cols.
// Warp grid 4m x 2n, warp tile 32x32. A smem-resident, B double-buffered.
// ---------------------------------------------------------------------------
#define SM_A     0
#define SM_B0    98304
#define SM_B1    147456
#define SM_TOTAL 196608

__global__ void __launch_bounds__(NT, 1) gemm_kernel(float* __restrict__ out) {
    extern __shared__ char smem[];
    __shared__ float zbuf[BM][2];
    __shared__ float cbuf[BM][2];
    __shared__ float red[8];

    const uint32_t sb = smem_u32(smem);
    const int tid  = threadIdx.x;
    const int lane = tid & 31;
    const int wid  = tid >> 5;
    const int wm   = wid & 3;        // 0..3  (32-row slices)
    const int wn   = wid >> 2;       // 0..1  (32-col slices)
    const int br0  = blockIdx.x * BM;
    const int td   = blockIdx.x >> 2;   // B tile holding this block's diagonal

    const char* gA = (const char*)g_A2;
    const char* gB = (const char*)g_B2;

    // ---- prologue: A tile + B tile 0 ----
    #pragma unroll
    for (int ii = 0; ii < (BM * NCH) / NT; ii++) {     // 24 iters
        int idx = ii * NT + tid;
        int c = idx % NCH, r = idx / NCH;
        CP16(sb + SM_A + r * 768 + ((c ^ (r & 7)) << 4),
             gA + (size_t)(br0 + r) * 768 + c * 16);
    }
    #pragma unroll
    for (int ii = 0; ii < (BN * NCH) / NT; ii++) {     // 6 iters
        int idx = ii * NT + tid;
        int c = idx % NCH, n = idx / NCH;
        CP16(sb + SM_B0 + n * 768 + ((c ^ (n & 7)) << 4),
             gB + (size_t)n * 768 + c * 16);
    }
    CP_COMMIT();

    // ---- per-thread fragment address bases ----
    uint32_t aBase[2], aS[2];
    #pragma unroll
    for (int mi = 0; mi < 2; mi++) {
        int row = wm * 32 + mi * 16 + (lane & 15);
        aBase[mi] = sb + SM_A + row * 768;
        aS[mi] = row & 7;
    }
    const uint32_t cbA = (lane >> 4);          // k-octet within k16
    uint32_t bOff[2], bS[2];
    #pragma unroll
    for (int j2 = 0; j2 < 2; j2++) {
        int n = wn * 32 + j2 * 16 + ((lane >> 4) & 1) * 8 + (lane & 7);
        bOff[j2] = n * 768;
        bS[j2] = n & 7;
    }
    const uint32_t cbB = (lane >> 3) & 1;

    // row slots: slot = mi*2 + h, row = wm*32 + mi*16 + h*8 + lane/4
    int rl[4], dc[4];
    float zsum[4], zcorr[4];
    #pragma unroll
    for (int sl = 0; sl < 4; sl++) {
        int mi = sl >> 1, h = sl & 1;
        rl[sl] = wm * 32 + mi * 16 + h * 8 + (lane >> 2);
        dc[sl] = (br0 + rl[sl]) >> 3;
        zsum[sl] = 0.f; zcorr[sl] = 0.f;
    }

    const uint32_t bufB[2] = { sb + SM_B0, sb + SM_B1 };

    for (int t = 0; t < NTILES; t++) {
        if (t + 1 < NTILES) {
            const uint32_t bb = bufB[(t + 1) & 1];
            #pragma unroll
            for (int ii = 0; ii < (BN * NCH) / NT; ii++) {
                int idx = ii * NT + tid;
                int c = idx % NCH, n = idx / NCH;
                CP16(bb + n * 768 + ((c ^ (n & 7)) << 4),
                     gB + (size_t)((t + 1) * BN + n) * 768 + c * 16);
            }
            CP_COMMIT();
            CP_WAIT1();
        } else {
            CP_WAIT0();
        }
        __syncthreads();

        const uint32_t bcur = bufB[t & 1];
        float acc[2][4][4];
        #pragma unroll
        for (int mi = 0; mi < 2; mi++)
            #pragma unroll
            for (int nj = 0; nj < 4; nj++)
                #pragma unroll
                for (int q = 0; q < 4; q++) acc[mi][nj][q] = 0.f;

        #pragma unroll
        for (int ks = 0; ks < KC / 16; ks++) {          // 24 steps
            const uint32_t c2 = 2u * ks;
            unsigned af[2][4], bf[2][4];
            #pragma unroll
            for (int mi = 0; mi < 2; mi++)
                ldsm4(af[mi], aBase[mi] + (((c2 | cbA) ^ aS[mi]) << 4));
            #pragma unroll
            for (int j2 = 0; j2 < 2; j2++)
                ldsm4(bf[j2], bcur + bOff[j2] + (((c2 | cbB) ^ bS[j2]) << 4));
            #pragma unroll
            for (int mi = 0; mi < 2; mi++)
                #pragma unroll
                for (int nj = 0; nj < 4; nj++)
                    mma16816(acc[mi][nj], af[mi],
                             bf[nj >> 1][(nj & 1) * 2], bf[nj >> 1][(nj & 1) * 2 + 1]);
        }

        // fused epilogue: clamp + exp + online Z (logits <= 30, no max pass)
        if (t == td) {
            #pragma unroll
            for (int mi = 0; mi < 2; mi++)
                #pragma unroll
                for (int nj = 0; nj < 4; nj++) {
                    int cb = t * BN + wn * 32 + nj * 8 + (lane & 3) * 2;
                    float e0 = __expf(fmaxf(acc[mi][nj][0], 1e-6f) - 30.f);
                    float e1 = __expf(fmaxf(acc[mi][nj][1], 1e-6f) - 30.f);
                    float e2 = __expf(fmaxf(acc[mi][nj][2], 1e-6f) - 30.f);
                    float e3 = __expf(fmaxf(acc[mi][nj][3], 1e-6f) - 30.f);
                    zsum[mi*2]   += e0 + e1;
                    zsum[mi*2+1] += e2 + e3;
                    if (cb     == dc[mi*2])   zcorr[mi*2]   += e0;
                    if (cb + 1 == dc[mi*2])   zcorr[mi*2]   += e1;
                    if (cb     == dc[mi*2+1]) zcorr[mi*2+1] += e2;
                    if (cb + 1 == dc[mi*2+1]) zcorr[mi*2+1] += e3;
                }
        } else {
            #pragma unroll
            for (int mi = 0; mi < 2; mi++)
                #pragma unroll
                for (int nj = 0; nj < 4; nj++) {
                    float e0 = __expf(fmaxf(acc[mi][nj][0], 1e-6f) - 30.f);
                    float e1 = __expf(fmaxf(acc[mi][nj][1], 1e-6f) - 30.f);
                    float e2 = __expf(fmaxf(acc[mi][nj][2], 1e-6f) - 30.f);
                    float e3 = __expf(fmaxf(acc[mi][nj][3], 1e-6f) - 30.f);
                    zsum[mi*2]   += e0 + e1;
                    zsum[mi*2+1] += e2 + e3;
                }
        }
        __syncthreads();
    }

    // reduce z across the 4 lanes of each quad (same row)
    #pragma unroll
    for (int sl = 0; sl < 4; sl++) {
        float z = zsum[sl], c = zcorr[sl];
        z += __shfl_xor_sync(0xffffffffu, z, 1);
        z += __shfl_xor_sync(0xffffffffu, z, 2);
        c += __shfl_xor_sync(0xffffffffu, c, 1);
        c += __shfl_xor_sync(0xffffffffu, c, 2);
        if ((lane & 3) == 0) { zbuf[rl[sl]][wn] = z; cbuf[rl[sl]][wn] = c; }
    }
    __syncthreads();

    // per-row loss + block reduce + single atomicAdd
    float loss = 0.f;
    if (tid < BM) {
        int row = br0 + tid;
        float lbl = g_lbl[row];
        float Z = zbuf[tid][0] + zbuf[tid][1] - cbuf[tid][0] - cbuf[tid][1]
                  + __expf(lbl - 30.f);
        loss = 30.f + logf(Z) - lbl;
    }
    #pragma unroll
    for (int off = 16; off > 0; off >>= 1)
        loss += __shfl_xor_sync(0xffffffffu, loss, off);
    if (lane == 0) red[wid] = loss;
    __syncthreads();
    if (tid == 0) {
        float tot = 0.f;
        #pragma unroll
        for (int q = 0; q < 8; q++) tot += red[q];
        atomicAdd(out, tot * (1.f / (float)NR));
    }
}

// ---------------------------------------------------------------------------
extern "C" void kernel_launch(void* const* d_in, const int* in_sizes, int n_in,
                              void* d_out, int out_size) {
    const float* x = (const float*)d_in[0];
    float* out = (float*)d_out;

    prep_kernel<<<NS, 128>>>(x, out);

    cudaFuncSetAttribute(gemm_kernel, cudaFuncAttributeMaxDynamicSharedMemorySize, SM_TOTAL);
    gemm_kernel<<<NR / BM, NT, SM_TOTAL>>>(out);
}